// round 12
// baseline (speedup 1.0000x reference)
#include <cuda_runtime.h>
#include <cuda.h>
#include <cstdint>

#define BB    256
#define NROWS 1024
#define INK   256
#define OUTN  256
#define NTILES2 (BB * (NROWS / 256))     // 1024 tiles of M=256

// SMEM layout (bytes) for tcgen05 path: 3 stages x (A 32KB + B 32KB)
#define SMEM_TMEM_PTR 0
#define SMEM_FULL(s)  (8  + 8 * (s))    // 3 barriers
#define SMEM_MDONE(s) (32 + 8 * (s))    // 3 barriers
#define SMEM_BIAS     64                // 256 floats -> [64, 1088)
#define SMEM_STG      2048
#define STAGE_SIZE    65536             // A[0,32768) + B[32768,65536)
#define A_OFF         0
#define B_OFF         32768
#define SMEM_TOTAL    (2048 + 3 * 65536)   // 198656
#define STAGE_BYTES   65536

#define TMEM_COLS 512

// 64MB transposed-weight scratch: wT[b][n][k] = tf32(w[indices[b]][k][n])
__device__ __align__(1024) float g_wT[(size_t)BB * OUTN * INK];

#if defined(__CUDA_ARCH__) && (defined(__CUDA_ARCH_FEAT_SM103_ALL) || \
    (defined(__CUDA_ARCH_SPECIFIC__)))
#define ALW_TCGEN05 1
#else
#define ALW_TCGEN05 0
#endif

// int64-vs-int32 index buffer detection (values < 1024 -> int64 high words all 0)
static __device__ __forceinline__ int fetch_index(const void* p, int b) {
    const int* q = (const int*)p;
    int odd_or = q[1] | q[3] | q[5] | q[7] | q[9] | q[11] | q[13] | q[15];
    return (odd_or == 0) ? q[2 * b] : q[b];
}

static __device__ __forceinline__ float tf32r(float f) {
    uint32_t u;
    asm("cvt.rna.tf32.f32 %0, %1;" : "=r"(u) : "f"(f));
    return __uint_as_float(u);
}

// ---------------- Kernel 1: gather + transpose + tf32-round ----------------
__global__ void __launch_bounds__(256)
alw_transpose(const void* __restrict__ indices, const float* __restrict__ w) {
    __shared__ float t[32][33];
    const int b    = blockIdx.y;
    const int tile = blockIdx.x;          // 0..63
    const int k0   = (tile >> 3) * 32;
    const int n0   = (tile & 7) * 32;
    const int ch   = fetch_index(indices, b);
    const int tx = threadIdx.x, ty = threadIdx.y;

    const float* __restrict__ src = w + (size_t)ch * INK * OUTN;
#pragma unroll
    for (int r = 0; r < 32; r += 8)
        t[ty + r][tx] = src[(size_t)(k0 + ty + r) * OUTN + n0 + tx];
    __syncthreads();

    float* __restrict__ dst = g_wT + (size_t)b * OUTN * INK;
#pragma unroll
    for (int r = 0; r < 32; r += 8)
        dst[(size_t)(n0 + ty + r) * INK + k0 + tx] = tf32r(t[tx][ty + r]);
}

#if ALW_TCGEN05

// tcgen05 idesc, kind::tf32: c=F32(1)@[4:5], a=TF32(2)@[7:9], b=TF32(2)@[10:12],
// N>>3 @[17:22], M>>4 @[24:28]; K-major both. M=128 per dispatch.
#define IDESC ((1u << 4) | (2u << 7) | (2u << 10) | ((OUTN / 8) << 17) | ((128 / 16) << 24))

// SW128 K-major smem descriptor base: layout=2, version=1, SBO=64, LBO=1
static __device__ __forceinline__ uint64_t make_desc(uint32_t addr) {
    const uint64_t base = (uint64_t(2) << 61) | (uint64_t(1) << 46) |
                          (uint64_t(64) << 32) | (uint64_t(1) << 16);
    return base | ((uint64_t)(addr >> 4) & 0x3FFF);
}

static __device__ __forceinline__ uint32_t smem_u32(const void* p) {
    uint32_t a;
    asm("{ .reg .u64 t; cvta.to.shared.u64 t, %1; cvt.u32.u64 %0, t; }" : "=r"(a) : "l"(p));
    return a;
}

#define MBARRIER_INIT(addr, cnt) \
    asm volatile("mbarrier.init.shared.b64 [%0], %1;" :: "r"((uint32_t)(addr)), "r"((uint32_t)(cnt)) : "memory")

#define MBARRIER_EXPECT_TX(addr, bytes) \
    asm volatile("mbarrier.arrive.expect_tx.shared.b64 _, [%0], %1;" \
                 :: "r"((uint32_t)(addr)), "r"((uint32_t)(bytes)) : "memory")

#define MBARRIER_WAIT_PARITY(mbar_addr, phase_parity) do {                                  \
    uint32_t _mbar = (uint32_t)(mbar_addr);                                                 \
    uint32_t _par  = (uint32_t)(phase_parity);                                              \
    uint32_t _done;                                                                         \
    asm volatile("{\n\t.reg .pred p;\n\t"                                                   \
                 "mbarrier.try_wait.parity.acquire.cta.shared::cta.b64 p, [%1], %2;\n\t"    \
                 "selp.b32 %0, 1, 0, p;\n\t}"                                               \
                 : "=r"(_done) : "r"(_mbar), "r"(_par) : "memory");                         \
    if (!_done) {                                                                           \
        asm volatile("{\n\t.reg .pred P1;\n\t"                                              \
            "WAIT_LOOP_%=:\n\t"                                                             \
            "mbarrier.try_wait.parity.acquire.cta.shared::cta.b64 P1, [%0], %1, 0x989680;\n\t" \
            "@P1 bra.uni WAIT_DONE_%=;\n\t"                                                 \
            "bra.uni WAIT_LOOP_%=;\n\t"                                                     \
            "WAIT_DONE_%=:\n\t}"                                                            \
            :: "r"(_mbar), "r"(_par) : "memory");                                           \
    }                                                                                       \
} while (0)

#define TMA_LOAD_3D(smem_addr, tmap_ptr, c0, c1, c2, mbar_addr) \
    asm volatile( \
        "cp.async.bulk.tensor.3d.shared::cta.global.tile.mbarrier::complete_tx::bytes " \
        "[%0], [%1, {%2, %3, %4}], [%5];" \
        :: "r"((uint32_t)(smem_addr)), "l"(tmap_ptr), \
           "r"((int32_t)(c0)), "r"((int32_t)(c1)), "r"((int32_t)(c2)), \
           "r"((uint32_t)(mbar_addr)) : "memory")

#define TCGEN05_ALLOC(smem_addr, ncols) \
    asm volatile("tcgen05.alloc.cta_group::1.sync.aligned.shared::cta.b32 [%0], %1;" \
                 :: "r"((uint32_t)(smem_addr)), "r"((uint32_t)(ncols)) : "memory")
#define TCGEN05_DEALLOC(tmem, ncols) \
    asm volatile("tcgen05.dealloc.cta_group::1.sync.aligned.b32 %0, %1;" \
                 :: "r"(tmem), "r"((uint32_t)(ncols)))
#define TCGEN05_RELINQ() \
    asm volatile("tcgen05.relinquish_alloc_permit.cta_group::1.sync.aligned;")
#define TCGEN05_COMMIT(mbar) \
    asm volatile("tcgen05.commit.cta_group::1.mbarrier::arrive::one.shared::cluster.b64 [%0];" \
                 :: "r"((uint32_t)(mbar)) : "memory")
#define TCGEN05_FENCE_AFTER() \
    asm volatile("tcgen05.fence::after_thread_sync;" ::: "memory")
#define TCGEN05_FENCE_BEFORE() \
    asm volatile("tcgen05.fence::before_thread_sync;" ::: "memory")
#define TCGEN05_WAIT_LD() \
    asm volatile("tcgen05.wait::ld.sync.aligned;" ::: "memory")
#define FENCE_PROXY_ASYNC() \
    asm volatile("fence.proxy.async.shared::cta;" ::: "memory")

#define TCGEN05_LD_32X32B_X32(r, tmem_addr) \
    asm volatile( \
        "tcgen05.ld.sync.aligned.32x32b.x32.b32 " \
        "{%0, %1, %2, %3, %4, %5, %6, %7, " \
        " %8, %9, %10, %11, %12, %13, %14, %15, " \
        " %16, %17, %18, %19, %20, %21, %22, %23, " \
        " %24, %25, %26, %27, %28, %29, %30, %31}, [%32];" \
        : "=r"((r)[0]),  "=r"((r)[1]),  "=r"((r)[2]),  "=r"((r)[3]), \
          "=r"((r)[4]),  "=r"((r)[5]),  "=r"((r)[6]),  "=r"((r)[7]), \
          "=r"((r)[8]),  "=r"((r)[9]),  "=r"((r)[10]), "=r"((r)[11]), \
          "=r"((r)[12]), "=r"((r)[13]), "=r"((r)[14]), "=r"((r)[15]), \
          "=r"((r)[16]), "=r"((r)[17]), "=r"((r)[18]), "=r"((r)[19]), \
          "=r"((r)[20]), "=r"((r)[21]), "=r"((r)[22]), "=r"((r)[23]), \
          "=r"((r)[24]), "=r"((r)[25]), "=r"((r)[26]), "=r"((r)[27]), \
          "=r"((r)[28]), "=r"((r)[29]), "=r"((r)[30]), "=r"((r)[31]) \
        : "r"(tmem_addr))

static __device__ __forceinline__ void mma_tf32_ss(uint32_t d_tmem, uint64_t a_desc,
                                                   uint64_t b_desc, uint32_t idesc,
                                                   uint32_t enable) {
    asm volatile(
        "{\n\t"
        ".reg .pred p;\n\t"
        "setp.ne.u32 p, %4, 0;\n\t"
        "tcgen05.mma.cta_group::1.kind::tf32 [%0], %1, %2, %3, {%5, %5, %5, %5}, p;\n\t"
        "}"
        :: "r"(d_tmem), "l"(a_desc), "l"(b_desc), "r"(idesc), "r"(enable), "r"(0u)
        : "memory");
}

#endif // ALW_TCGEN05

// -- Kernel 2: PERSISTENT M=256/CTA, 3-stage async ring, tcgen05 GEMM --------
__global__ void __launch_bounds__(512, 1)
alw_main(const __grid_constant__ CUtensorMap tmapA,
         const __grid_constant__ CUtensorMap tmapB,
         const float* __restrict__ x,
         const void*  __restrict__ indices,
         const float* __restrict__ w,
         const float* __restrict__ bias,
         float* __restrict__ out) {
#if ALW_TCGEN05
    extern __shared__ char smem[];
    const uint32_t sb = smem_u32(smem);
    const int tid  = threadIdx.x;
    const int lane = tid & 31;
    const int wid  = tid >> 5;
    const int grid = gridDim.x;
    const int bid  = blockIdx.x;

    // one-time prologue
    if (wid == 0) {
        TCGEN05_ALLOC(sb + SMEM_TMEM_PTR, TMEM_COLS);
        TCGEN05_RELINQ();
    }
    if (tid == 0) {
#pragma unroll
        for (int s = 0; s < 3; ++s) {
            MBARRIER_INIT(sb + SMEM_FULL(s), 1);
            MBARRIER_INIT(sb + SMEM_MDONE(s), 1);
        }
        FENCE_PROXY_ASYNC();
    }
    __syncthreads();
    uint32_t tmem;
    asm volatile("ld.shared.b32 %0, [%1];" : "=r"(tmem) : "r"(sb + SMEM_TMEM_PTR));

    // producer state (tid 0): stage cursor, per-stage parity bitmasks, chunk idx
    int s_cur = 0;
    uint32_t pf = 0, pd = 0;
    int ci = 0;
    const int my_ntiles = (bid < NTILES2) ? ((NTILES2 - 1 - bid) / grid + 1) : 0;
    const int total_ch  = my_ntiles * 8;

    // pre-issue chunks 0,1,2 of the first tile into stages 0,1,2
    if (tid == 0 && my_ntiles > 0) {
        const int b0 = bid >> 2, mp0 = bid & 3;
#pragma unroll
        for (int s = 0; s < 3; ++s) {
            const uint32_t stg = sb + SMEM_STG + s * STAGE_SIZE;
            MBARRIER_EXPECT_TX(sb + SMEM_FULL(s), STAGE_BYTES);
            TMA_LOAD_3D(stg + A_OFF, &tmapA, s * 32, mp0 * 256, b0, sb + SMEM_FULL(s));
            TMA_LOAD_3D(stg + B_OFF, &tmapB, s * 32, 0, b0, sb + SMEM_FULL(s));
        }
    }

    // epilogue constants (R9-validated mapping)
    const int dtile = wid >> 3;
    const int w8    = wid & 7;
    const int sub   = w8 & 3;
    const int half  = w8 >> 2;
    const uint32_t woff  = (uint32_t)sub << 21;
    const uint32_t dbase = (uint32_t)dtile * 256;
    const float* sbias = (const float*)(smem + SMEM_BIAS);

#pragma unroll 1
    for (int tile = bid; tile < NTILES2; tile += grid) {
        const int b  = tile >> 2;
        const int mp = tile & 3;
        const int ch = fetch_index(indices, b);

        if (tid < 256)
            ((float*)(smem + SMEM_BIAS))[tid] = bias[(size_t)ch * OUTN + tid];

        if (tid == 0) {
#pragma unroll 1
            for (int kt = 0; kt < 8; ++kt) {
                const int s = s_cur;
                const uint32_t stg = sb + SMEM_STG + s * STAGE_SIZE;

                // consume chunk ci (stage s)
                MBARRIER_WAIT_PARITY(sb + SMEM_FULL(s), (pf >> s) & 1);
                pf ^= (1u << s);

                uint64_t ad0 = make_desc(stg + A_OFF);            // rows 0-127
                uint64_t ad1 = make_desc(stg + A_OFF + 16384);    // rows 128-255
                uint64_t bd  = make_desc(stg + B_OFF);
#pragma unroll
                for (int kk = 0; kk < 4; ++kk) {
                    const uint32_t en = (uint32_t)((kt | kk) != 0);
                    mma_tf32_ss(tmem,       ad0 + kk * 2, bd + kk * 2, IDESC, en);
                    mma_tf32_ss(tmem + 256, ad1 + kk * 2, bd + kk * 2, IDESC, en);
                }
                TCGEN05_COMMIT(sb + SMEM_MDONE(s));

                // wait MMA done, then refill stage s with chunk ci+3
                MBARRIER_WAIT_PARITY(sb + SMEM_MDONE(s), (pd >> s) & 1);
                pd ^= (1u << s);

                const int nci = ci + 3;
                if (nci < total_ch) {
                    const int q   = nci >> 3;
                    const int kt2 = nci & 7;
                    const int t2  = bid + q * grid;
                    const int b2  = t2 >> 2;
                    const int mp2 = t2 & 3;
                    MBARRIER_EXPECT_TX(sb + SMEM_FULL(s), STAGE_BYTES);
                    TMA_LOAD_3D(stg + A_OFF, &tmapA, kt2 * 32, mp2 * 256, b2,
                                sb + SMEM_FULL(s));
                    TMA_LOAD_3D(stg + B_OFF, &tmapB, kt2 * 32, 0, b2,
                                sb + SMEM_FULL(s));
                }
                ++ci;
                s_cur = (s_cur == 2) ? 0 : s_cur + 1;
            }
        }

        __syncthreads();          // producer observed last commit; bias written
        TCGEN05_FENCE_AFTER();

        // ---- epilogue: 16 warps drain both accumulators; next TMAs in flight ----
        const int m = mp * 256 + dtile * 128 + sub * 32 + lane;
        float* __restrict__ orow = out + ((size_t)b * NROWS + m) * OUTN;

#pragma unroll
        for (int g = 0; g < 4; ++g) {
            const int c0 = half * 128 + g * 32;
            uint32_t d[32];
            TCGEN05_LD_32X32B_X32(d, tmem + woff + dbase + (uint32_t)c0);
            TCGEN05_WAIT_LD();
#pragma unroll
            for (int q = 0; q < 8; ++q) {
                float4 v;
                v.x = __uint_as_float(d[q * 4 + 0]) + sbias[c0 + q * 4 + 0];
                v.y = __uint_as_float(d[q * 4 + 1]) + sbias[c0 + q * 4 + 1];
                v.z = __uint_as_float(d[q * 4 + 2]) + sbias[c0 + q * 4 + 2];
                v.w = __uint_as_float(d[q * 4 + 3]) + sbias[c0 + q * 4 + 3];
                *(float4*)(orow + c0 + q * 4) = v;
            }
        }

        TCGEN05_FENCE_BEFORE();
        __syncthreads();          // TMEM free for next tile; bias rewritable
    }

    if (wid == 0) {
        TCGEN05_DEALLOC(tmem, TMEM_COLS);
    }

#else  // ---------------- fallback: correct smem-tiled FFMA (plain sm_103) ----
    extern __shared__ float fsmem[];
    float* As = fsmem;                  // [256][33]
    float* Bs = fsmem + 256 * 33;       // [32][132]

    const int tid = threadIdx.x;
    const int r0 = (tid >> 4) * 8;
    const int c0 = (tid & 15) * 8;

    for (int tile = blockIdx.x; tile < NTILES2; tile += gridDim.x) {
        const int b  = tile >> 2;
        const int mp = tile & 3;
        const int ch = fetch_index(indices, b);

        const float* __restrict__ xb = x + ((size_t)b * NROWS + mp * 256) * INK;
        const float* __restrict__ wb = w + (size_t)ch * (INK * OUTN);

        for (int ng = 0; ng < 2; ++ng) {
            float acc[8][8];
#pragma unroll
            for (int i = 0; i < 8; ++i)
#pragma unroll
                for (int j = 0; j < 8; ++j) acc[i][j] = 0.0f;

            for (int kt = 0; kt < 8; ++kt) {
                __syncthreads();
                for (int i = tid; i < 256 * 32; i += 512) {
                    int row = i >> 5, col = i & 31;
                    As[row * 33 + col] = xb[(size_t)row * INK + kt * 32 + col];
                }
                for (int i = tid; i < 32 * 128; i += 512) {
                    int row = i >> 7, col = i & 127;
                    Bs[row * 132 + col] = wb[(size_t)(kt * 32 + row) * OUTN + ng * 128 + col];
                }
                __syncthreads();
#pragma unroll 8
                for (int kk = 0; kk < 32; ++kk) {
                    float av[8], bv[8];
#pragma unroll
                    for (int i = 0; i < 8; ++i) av[i] = As[(r0 + i) * 33 + kk];
#pragma unroll
                    for (int j = 0; j < 8; ++j) bv[j] = Bs[kk * 132 + c0 + j];
#pragma unroll
                    for (int i = 0; i < 8; ++i)
#pragma unroll
                        for (int j = 0; j < 8; ++j) acc[i][j] += av[i] * bv[j];
                }
            }

#pragma unroll
            for (int i = 0; i < 8; ++i) {
                float* orow = out + ((size_t)b * NROWS + mp * 256 + r0 + i) * OUTN + ng * 128 + c0;
#pragma unroll
                for (int j = 0; j < 8; ++j)
                    orow[j] = acc[i][j] + bias[(size_t)ch * OUTN + ng * 128 + c0 + j];
            }
            __syncthreads();
        }
    }
#endif
}

// ---------------- host ----------------
typedef CUresult (*PFN_encodeTiled)(
    CUtensorMap*, CUtensorMapDataType, cuuint32_t, void*,
    const cuuint64_t*, const cuuint64_t*, const cuuint32_t*, const cuuint32_t*,
    CUtensorMapInterleave, CUtensorMapSwizzle, CUtensorMapL2promotion,
    CUtensorMapFloatOOBfill);

extern "C" void kernel_launch(void* const* d_in, const int* in_sizes, int n_in,
                              void* d_out, int out_size) {
    const float* x       = (const float*)d_in[0];
    const void*  indices = d_in[1];
    const float* w       = (const float*)d_in[2];
    const float* bias    = (const float*)d_in[3];
    float* out = (float*)d_out;

    static PFN_encodeTiled enc = nullptr;
    static int nsm = 0;
    if (!enc) {
        void* p = nullptr;
        cudaDriverEntryPointQueryResult qr;
        cudaGetDriverEntryPoint("cuTensorMapEncodeTiled", &p, cudaEnableDefault, &qr);
        enc = (PFN_encodeTiled)p;
        int dev = 0;
        cudaGetDevice(&dev);
        cudaDeviceGetAttribute(&nsm, cudaDevAttrMultiProcessorCount, dev);
    }

    void* wT_ptr = nullptr;
    cudaGetSymbolAddress(&wT_ptr, g_wT);

    // A tensormap: x as [b=256][row=1024][k=256] f32, box (32k, 256rows, 1b), SW128
    CUtensorMap tmapA;
    {
        cuuint64_t dims[3]    = {INK, NROWS, BB};
        cuuint64_t strides[2] = {(cuuint64_t)INK * 4, (cuuint64_t)INK * NROWS * 4};
        cuuint32_t box[3]     = {32, 256, 1};
        cuuint32_t estr[3]    = {1, 1, 1};
        enc(&tmapA, CU_TENSOR_MAP_DATA_TYPE_FLOAT32, 3, (void*)x, dims, strides, box, estr,
            CU_TENSOR_MAP_INTERLEAVE_NONE, CU_TENSOR_MAP_SWIZZLE_128B,
            CU_TENSOR_MAP_L2_PROMOTION_L2_128B, CU_TENSOR_MAP_FLOAT_OOB_FILL_NONE);
    }

    // B tensormap: g_wT as [b=256][n=256][k=256] f32, box (32k, 256n, 1b), SW128
    CUtensorMap tmapB;
    {
        cuuint64_t dims[3]    = {INK, OUTN, BB};
        cuuint64_t strides[2] = {(cuuint64_t)INK * 4, (cuuint64_t)INK * OUTN * 4};
        cuuint32_t box[3]     = {32, 256, 1};
        cuuint32_t estr[3]    = {1, 1, 1};
        enc(&tmapB, CU_TENSOR_MAP_DATA_TYPE_FLOAT32, 3, wT_ptr, dims, strides, box, estr,
            CU_TENSOR_MAP_INTERLEAVE_NONE, CU_TENSOR_MAP_SWIZZLE_128B,
            CU_TENSOR_MAP_L2_PROMOTION_L2_128B, CU_TENSOR_MAP_FLOAT_OOB_FILL_NONE);
    }

    // pass 1: gather + transpose + tf32-round weights
    alw_transpose<<<dim3(64, BB), dim3(32, 8)>>>(indices, w);

    // pass 2: persistent GEMM, 1 CTA per SM (M=256, full TMEM, 3-stage ring)
    cudaFuncSetAttribute(alw_main,
                         cudaFuncAttributeMaxDynamicSharedMemorySize, SMEM_TOTAL);
    int grid = (nsm > 0 ? nsm : 148);
    if (grid > NTILES2) grid = NTILES2;
    alw_main<<<grid, 512, SMEM_TOTAL>>>(tmapA, tmapB, x, indices, w, bias, out);
}

// round 13
// speedup vs baseline: 1.1040x; 1.1040x over previous
#include <cuda_runtime.h>
#include <cuda.h>
#include <cstdint>

#define BB    256
#define NROWS 1024
#define INK   256
#define OUTN  256
#define NTILES (BB * (NROWS / 128))      // 2048

// SMEM layout (bytes) for tcgen05 path
#define SMEM_TMEM_PTR 0
#define SMEM_FULL(s)  (8  + 8 * (s))    // 2 barriers
#define SMEM_MDONE(s) (24 + 8 * (s))    // 2 barriers
#define SMEM_BIAS     64                // 256 floats
#define SMEM_A        2048              // 2 stages x 16KB (128 rows x 128B, SW128)
#define A_STAGE       16384
#define SMEM_B        34816             // 2 stages x 32KB (256 rows x 128B, SW128)
#define B_STAGE       32768
#define SMEM_TOTAL    100352
#define STAGE_BYTES   (A_STAGE + B_STAGE)   // 49152 expect_tx per stage

#define TMEM_COLS 256

// 64MB transposed-weight scratch: wT[b][n][k] = tf32(w[indices[b]][k][n])
__device__ __align__(1024) float g_wT[(size_t)BB * OUTN * INK];

#if defined(__CUDA_ARCH__) && (defined(__CUDA_ARCH_FEAT_SM103_ALL) || \
    (defined(__CUDA_ARCH_SPECIFIC__)))
#define ALW_TCGEN05 1
#else
#define ALW_TCGEN05 0
#endif

// int64-vs-int32 index buffer detection (values < 1024 -> int64 high words all 0)
static __device__ __forceinline__ int fetch_index(const void* p, int b) {
    const int* q = (const int*)p;
    int odd_or = q[1] | q[3] | q[5] | q[7] | q[9] | q[11] | q[13] | q[15];
    return (odd_or == 0) ? q[2 * b] : q[b];
}

static __device__ __forceinline__ float tf32r(float f) {
    uint32_t u;
    asm("cvt.rna.tf32.f32 %0, %1;" : "=r"(u) : "f"(f));
    return __uint_as_float(u);
}

// ---------------- Kernel 1: gather + transpose + tf32-round (vectorized) ----
// 64x64 tiles, float4 global reads AND writes; tf32 rounding at the write,
// numerically identical to the previous scalar version.
__global__ void __launch_bounds__(256)
alw_transpose(const void* __restrict__ indices, const float* __restrict__ w) {
    __shared__ float s[64][65];
    const int b    = blockIdx.y;
    const int tile = blockIdx.x;          // 0..15
    const int k0   = (tile >> 2) * 64;
    const int n0   = (tile & 3) * 64;
    const int ch   = fetch_index(indices, b);
    const int tid  = threadIdx.x;

    const float* __restrict__ src = w + (size_t)ch * INK * OUTN;
#pragma unroll
    for (int i = 0; i < 4; ++i) {
        int idx = i * 256 + tid;
        int r  = idx >> 4;        // k offset within tile, 0..63
        int c4 = idx & 15;        // n float4 offset, 0..15
        float4 v = *(const float4*)(src + (size_t)(k0 + r) * OUTN + n0 + c4 * 4);
        s[c4 * 4 + 0][r] = v.x;
        s[c4 * 4 + 1][r] = v.y;
        s[c4 * 4 + 2][r] = v.z;
        s[c4 * 4 + 3][r] = v.w;
    }
    __syncthreads();

    float* __restrict__ dst = g_wT + (size_t)b * OUTN * INK;
#pragma unroll
    for (int i = 0; i < 4; ++i) {
        int idx = i * 256 + tid;
        int rn = idx >> 4;        // n offset within tile, 0..63
        int c4 = idx & 15;        // k float4 offset, 0..15
        float4 v;
        v.x = tf32r(s[rn][c4 * 4 + 0]);
        v.y = tf32r(s[rn][c4 * 4 + 1]);
        v.z = tf32r(s[rn][c4 * 4 + 2]);
        v.w = tf32r(s[rn][c4 * 4 + 3]);
        *(float4*)(dst + (size_t)(n0 + rn) * INK + k0 + c4 * 4) = v;
    }
}

#if ALW_TCGEN05

// tcgen05 idesc, kind::tf32: c=F32(1)@[4:5], a=TF32(2)@[7:9], b=TF32(2)@[10:12],
// N>>3 @[17:22], M>>4 @[24:28]; K-major both. M=128 per dispatch.
#define IDESC ((1u << 4) | (2u << 7) | (2u << 10) | ((OUTN / 8) << 17) | ((128 / 16) << 24))

// SW128 K-major smem descriptor base: layout=2, version=1, SBO=64, LBO=1
static __device__ __forceinline__ uint64_t make_desc(uint32_t addr) {
    const uint64_t base = (uint64_t(2) << 61) | (uint64_t(1) << 46) |
                          (uint64_t(64) << 32) | (uint64_t(1) << 16);
    return base | ((uint64_t)(addr >> 4) & 0x3FFF);
}

static __device__ __forceinline__ uint32_t smem_u32(const void* p) {
    uint32_t a;
    asm("{ .reg .u64 t; cvta.to.shared.u64 t, %1; cvt.u32.u64 %0, t; }" : "=r"(a) : "l"(p));
    return a;
}

#define MBARRIER_INIT(addr, cnt) \
    asm volatile("mbarrier.init.shared.b64 [%0], %1;" :: "r"((uint32_t)(addr)), "r"((uint32_t)(cnt)) : "memory")

#define MBARRIER_EXPECT_TX(addr, bytes) \
    asm volatile("mbarrier.arrive.expect_tx.shared.b64 _, [%0], %1;" \
                 :: "r"((uint32_t)(addr)), "r"((uint32_t)(bytes)) : "memory")

#define MBARRIER_WAIT_PARITY(mbar_addr, phase_parity) do {                                  \
    uint32_t _mbar = (uint32_t)(mbar_addr);                                                 \
    uint32_t _par  = (uint32_t)(phase_parity);                                              \
    uint32_t _done;                                                                         \
    asm volatile("{\n\t.reg .pred p;\n\t"                                                   \
                 "mbarrier.try_wait.parity.acquire.cta.shared::cta.b64 p, [%1], %2;\n\t"    \
                 "selp.b32 %0, 1, 0, p;\n\t}"                                               \
                 : "=r"(_done) : "r"(_mbar), "r"(_par) : "memory");                         \
    if (!_done) {                                                                           \
        asm volatile("{\n\t.reg .pred P1;\n\t"                                              \
            "WAIT_LOOP_%=:\n\t"                                                             \
            "mbarrier.try_wait.parity.acquire.cta.shared::cta.b64 P1, [%0], %1, 0x989680;\n\t" \
            "@P1 bra.uni WAIT_DONE_%=;\n\t"                                                 \
            "bra.uni WAIT_LOOP_%=;\n\t"                                                     \
            "WAIT_DONE_%=:\n\t}"                                                            \
            :: "r"(_mbar), "r"(_par) : "memory");                                           \
    }                                                                                       \
} while (0)

#define TMA_LOAD_3D(smem_addr, tmap_ptr, c0, c1, c2, mbar_addr) \
    asm volatile( \
        "cp.async.bulk.tensor.3d.shared::cta.global.tile.mbarrier::complete_tx::bytes " \
        "[%0], [%1, {%2, %3, %4}], [%5];" \
        :: "r"((uint32_t)(smem_addr)), "l"(tmap_ptr), \
           "r"((int32_t)(c0)), "r"((int32_t)(c1)), "r"((int32_t)(c2)), \
           "r"((uint32_t)(mbar_addr)) : "memory")

#define TCGEN05_ALLOC(smem_addr, ncols) \
    asm volatile("tcgen05.alloc.cta_group::1.sync.aligned.shared::cta.b32 [%0], %1;" \
                 :: "r"((uint32_t)(smem_addr)), "r"((uint32_t)(ncols)) : "memory")
#define TCGEN05_DEALLOC(tmem, ncols) \
    asm volatile("tcgen05.dealloc.cta_group::1.sync.aligned.b32 %0, %1;" \
                 :: "r"(tmem), "r"((uint32_t)(ncols)))
#define TCGEN05_RELINQ() \
    asm volatile("tcgen05.relinquish_alloc_permit.cta_group::1.sync.aligned;")
#define TCGEN05_COMMIT(mbar) \
    asm volatile("tcgen05.commit.cta_group::1.mbarrier::arrive::one.shared::cluster.b64 [%0];" \
                 :: "r"((uint32_t)(mbar)) : "memory")
#define TCGEN05_FENCE_AFTER() \
    asm volatile("tcgen05.fence::after_thread_sync;" ::: "memory")
#define TCGEN05_FENCE_BEFORE() \
    asm volatile("tcgen05.fence::before_thread_sync;" ::: "memory")
#define TCGEN05_WAIT_LD() \
    asm volatile("tcgen05.wait::ld.sync.aligned;" ::: "memory")
#define FENCE_PROXY_ASYNC() \
    asm volatile("fence.proxy.async.shared::cta;" ::: "memory")

#define TCGEN05_LD_32X32B_X32(r, tmem_addr) \
    asm volatile( \
        "tcgen05.ld.sync.aligned.32x32b.x32.b32 " \
        "{%0, %1, %2, %3, %4, %5, %6, %7, " \
        " %8, %9, %10, %11, %12, %13, %14, %15, " \
        " %16, %17, %18, %19, %20, %21, %22, %23, " \
        " %24, %25, %26, %27, %28, %29, %30, %31}, [%32];" \
        : "=r"((r)[0]),  "=r"((r)[1]),  "=r"((r)[2]),  "=r"((r)[3]), \
          "=r"((r)[4]),  "=r"((r)[5]),  "=r"((r)[6]),  "=r"((r)[7]), \
          "=r"((r)[8]),  "=r"((r)[9]),  "=r"((r)[10]), "=r"((r)[11]), \
          "=r"((r)[12]), "=r"((r)[13]), "=r"((r)[14]), "=r"((r)[15]), \
          "=r"((r)[16]), "=r"((r)[17]), "=r"((r)[18]), "=r"((r)[19]), \
          "=r"((r)[20]), "=r"((r)[21]), "=r"((r)[22]), "=r"((r)[23]), \
          "=r"((r)[24]), "=r"((r)[25]), "=r"((r)[26]), "=r"((r)[27]), \
          "=r"((r)[28]), "=r"((r)[29]), "=r"((r)[30]), "=r"((r)[31]) \
        : "r"(tmem_addr))

static __device__ __forceinline__ void mma_tf32_ss(uint32_t d_tmem, uint64_t a_desc,
                                                   uint64_t b_desc, uint32_t idesc,
                                                   uint32_t enable) {
    asm volatile(
        "{\n\t"
        ".reg .pred p;\n\t"
        "setp.ne.u32 p, %4, 0;\n\t"
        "tcgen05.mma.cta_group::1.kind::tf32 [%0], %1, %2, %3, {%5, %5, %5, %5}, p;\n\t"
        "}"
        :: "r"(d_tmem), "l"(a_desc), "l"(b_desc), "r"(idesc), "r"(enable), "r"(0u)
        : "memory");
}

#endif // ALW_TCGEN05

// ------- Kernel 2: PERSISTENT fully-async tcgen05 GEMM (TMA A + TMA B) -------
__global__ void __launch_bounds__(256, 2)
alw_main(const __grid_constant__ CUtensorMap tmapA,
         const __grid_constant__ CUtensorMap tmapB,
         const float* __restrict__ x,
         const void*  __restrict__ indices,
         const float* __restrict__ w,
         const float* __restrict__ bias,
         float* __restrict__ out) {
#if ALW_TCGEN05
    extern __shared__ char smem[];
    const uint32_t sb = smem_u32(smem);
    const int tid  = threadIdx.x;
    const int lane = tid & 31;
    const int wid  = tid >> 5;
    const int stride = gridDim.x;

    // one-time prologue
    if (wid == 0) {
        TCGEN05_ALLOC(sb + SMEM_TMEM_PTR, TMEM_COLS);
        TCGEN05_RELINQ();
    }
    if (tid == 0) {
        MBARRIER_INIT(sb + SMEM_FULL(0), 1);
        MBARRIER_INIT(sb + SMEM_FULL(1), 1);
        MBARRIER_INIT(sb + SMEM_MDONE(0), 1);
        MBARRIER_INIT(sb + SMEM_MDONE(1), 1);
        FENCE_PROXY_ASYNC();
    }
    __syncthreads();
    uint32_t tmem;
    asm volatile("ld.shared.b32 %0, [%1];" : "=r"(tmem) : "r"(sb + SMEM_TMEM_PTR));

    // producer phase counters (only tid 0 uses them)
    int fullp0 = 0, fullp1 = 0, donep0 = 0, donep1 = 0;
    int first = 1;

    // epilogue constants
    const int sub  = wid & 3;
    const int half = wid >> 2;
    const uint32_t woff = (uint32_t)sub << 21;
    const float* sbias = (const float*)(smem + SMEM_BIAS);

#pragma unroll 1
    for (int tile = blockIdx.x; tile < NTILES; tile += stride) {
        const int b     = tile >> 3;
        const int mtile = tile & 7;
        const int ch    = fetch_index(indices, b);

        // bias for this tile (read in epilogue after the mid-tile syncthreads)
        ((float*)(smem + SMEM_BIAS))[tid] = bias[(size_t)ch * OUTN + tid];

        if (tid == 0) {
            if (first) {
                // cold start: issue chunks 0,1 of the first tile
#pragma unroll
                for (int s = 0; s < 2; ++s) {
                    MBARRIER_EXPECT_TX(sb + SMEM_FULL(s), STAGE_BYTES);
                    TMA_LOAD_3D(sb + SMEM_A + s * A_STAGE, &tmapA,
                                s * 32, mtile * 128, b, sb + SMEM_FULL(s));
                    TMA_LOAD_3D(sb + SMEM_B + s * B_STAGE, &tmapB,
                                s * 32, 0, b, sb + SMEM_FULL(s));
                }
                first = 0;
            }
            // else: chunks 0,1 of this tile were issued at the tail of the
            // previous tile's chunk loop (kt = 6, 7) and ran under its epilogue.

            const int ntile   = tile + stride;
            const int nb      = (ntile < NTILES) ? (ntile >> 3) : 0;
            const int nmtile  = (ntile < NTILES) ? (ntile & 7) : 0;
            const int have_nt = (ntile < NTILES);

#pragma unroll 1
            for (int kt = 0; kt < 8; ++kt) {
                const int s = kt & 1;
                const uint32_t bfull = sb + SMEM_FULL(s);
                const uint32_t mdone = sb + SMEM_MDONE(s);

                // consume chunk kt
                if (s == 0) { MBARRIER_WAIT_PARITY(bfull, fullp0); fullp0 ^= 1; }
                else        { MBARRIER_WAIT_PARITY(bfull, fullp1); fullp1 ^= 1; }

                uint64_t ad = make_desc(sb + SMEM_A + s * A_STAGE);
                uint64_t bd = make_desc(sb + SMEM_B + s * B_STAGE);
#pragma unroll
                for (int kk = 0; kk < 4; ++kk) {
                    mma_tf32_ss(tmem, ad + kk * 2, bd + kk * 2, IDESC,
                                (uint32_t)((kt | kk) != 0));
                }
                TCGEN05_COMMIT(mdone);

                // wait for this chunk's MMA, then refill the stage:
                // kt<6 -> chunk kt+2 of this tile; kt>=6 -> chunk kt-6 of next tile
                if (s == 0) { MBARRIER_WAIT_PARITY(mdone, donep0); donep0 ^= 1; }
                else        { MBARRIER_WAIT_PARITY(mdone, donep1); donep1 ^= 1; }

                if (kt < 6) {
                    MBARRIER_EXPECT_TX(bfull, STAGE_BYTES);
                    TMA_LOAD_3D(sb + SMEM_A + s * A_STAGE, &tmapA,
                                (kt + 2) * 32, mtile * 128, b, bfull);
                    TMA_LOAD_3D(sb + SMEM_B + s * B_STAGE, &tmapB,
                                (kt + 2) * 32, 0, b, bfull);
                } else if (have_nt) {
                    MBARRIER_EXPECT_TX(bfull, STAGE_BYTES);
                    TMA_LOAD_3D(sb + SMEM_A + s * A_STAGE, &tmapA,
                                (kt - 6) * 32, nmtile * 128, nb, bfull);
                    TMA_LOAD_3D(sb + SMEM_B + s * B_STAGE, &tmapB,
                                (kt - 6) * 32, 0, nb, bfull);
                }
            }
            // producer has observed the final commit (kt=7 mdone wait above)
        }

        __syncthreads();          // MMA results + bias visible to all
        TCGEN05_FENCE_AFTER();

        // ---- epilogue: 8 warps drain TMEM + bias, next tile's TMA in flight ----
        const int m = mtile * 128 + sub * 32 + lane;
        float* __restrict__ orow = out + ((size_t)b * NROWS + m) * OUTN;

#pragma unroll
        for (int g = 0; g < 4; ++g) {
            const int c0 = half * 128 + g * 32;
            uint32_t d[32];
            TCGEN05_LD_32X32B_X32(d, tmem + woff + (uint32_t)c0);
            TCGEN05_WAIT_LD();
#pragma unroll
            for (int q = 0; q < 8; ++q) {
                float4 v;
                v.x = __uint_as_float(d[q * 4 + 0]) + sbias[c0 + q * 4 + 0];
                v.y = __uint_as_float(d[q * 4 + 1]) + sbias[c0 + q * 4 + 1];
                v.z = __uint_as_float(d[q * 4 + 2]) + sbias[c0 + q * 4 + 2];
                v.w = __uint_as_float(d[q * 4 + 3]) + sbias[c0 + q * 4 + 3];
                *(float4*)(orow + c0 + q * 4) = v;
            }
        }

        TCGEN05_FENCE_BEFORE();
        __syncthreads();          // TMEM free for next tile's MMA; bias rewritable
    }

    if (wid == 0) {
        TCGEN05_DEALLOC(tmem, TMEM_COLS);
    }

#else  // ---------------- fallback: correct smem-tiled FFMA (plain sm_103) ----
    extern __shared__ float fsmem[];
    float* As = fsmem;                  // [128][33]
    float* Bs = fsmem + 128 * 33;       // [32][132]

    const int tid = threadIdx.x;
    const int r0 = (tid >> 4) * 8;
    const int c0 = (tid & 15) * 8;

    for (int tile = blockIdx.x; tile < NTILES; tile += gridDim.x) {
        const int b     = tile >> 3;
        const int mtile = tile & 7;
        const int ch    = fetch_index(indices, b);

        const float* __restrict__ xb = x + ((size_t)b * NROWS + mtile * 128) * INK;
        const float* __restrict__ wb = w + (size_t)ch * (INK * OUTN);

        for (int ng = 0; ng < 2; ++ng) {
            float acc[8][8];
#pragma unroll
            for (int i = 0; i < 8; ++i)
#pragma unroll
                for (int j = 0; j < 8; ++j) acc[i][j] = 0.0f;

            for (int kt = 0; kt < 8; ++kt) {
                __syncthreads();
                for (int i = tid; i < 128 * 32; i += 256) {
                    int row = i >> 5, col = i & 31;
                    As[row * 33 + col] = xb[(size_t)row * INK + kt * 32 + col];
                }
                for (int i = tid; i < 32 * 128; i += 256) {
                    int row = i >> 7, col = i & 127;
                    Bs[row * 132 + col] = wb[(size_t)(kt * 32 + row) * OUTN + ng * 128 + col];
                }
                __syncthreads();
#pragma unroll 8
                for (int kk = 0; kk < 32; ++kk) {
                    float av[8], bv[8];
#pragma unroll
                    for (int i = 0; i < 8; ++i) av[i] = As[(r0 + i) * 33 + kk];
#pragma unroll
                    for (int j = 0; j < 8; ++j) bv[j] = Bs[kk * 132 + c0 + j];
#pragma unroll
                    for (int i = 0; i < 8; ++i)
#pragma unroll
                        for (int j = 0; j < 8; ++j) acc[i][j] += av[i] * bv[j];
                }
            }

#pragma unroll
            for (int i = 0; i < 8; ++i) {
                float* orow = out + ((size_t)b * NROWS + mtile * 128 + r0 + i) * OUTN + ng * 128 + c0;
#pragma unroll
                for (int j = 0; j < 8; ++j)
                    orow[j] = acc[i][j] + bias[(size_t)ch * OUTN + ng * 128 + c0 + j];
            }
            __syncthreads();
        }
    }
#endif
}

// ---------------- host ----------------
typedef CUresult (*PFN_encodeTiled)(
    CUtensorMap*, CUtensorMapDataType, cuuint32_t, void*,
    const cuuint64_t*, const cuuint64_t*, const cuuint32_t*, const cuuint32_t*,
    CUtensorMapInterleave, CUtensorMapSwizzle, CUtensorMapL2promotion,
    CUtensorMapFloatOOBfill);

extern "C" void kernel_launch(void* const* d_in, const int* in_sizes, int n_in,
                              void* d_out, int out_size) {
    const float* x       = (const float*)d_in[0];
    const void*  indices = d_in[1];
    const float* w       = (const float*)d_in[2];
    const float* bias    = (const float*)d_in[3];
    float* out = (float*)d_out;

    static PFN_encodeTiled enc = nullptr;
    static int nsm = 0;
    if (!enc) {
        void* p = nullptr;
        cudaDriverEntryPointQueryResult qr;
        cudaGetDriverEntryPoint("cuTensorMapEncodeTiled", &p, cudaEnableDefault, &qr);
        enc = (PFN_encodeTiled)p;
        int dev = 0;
        cudaGetDevice(&dev);
        cudaDeviceGetAttribute(&nsm, cudaDevAttrMultiProcessorCount, dev);
    }

    void* wT_ptr = nullptr;
    cudaGetSymbolAddress(&wT_ptr, g_wT);

    // A tensormap: x as [b=256][row=1024][k=256] f32, box (32k, 128rows, 1b), SW128
    CUtensorMap tmapA;
    {
        cuuint64_t dims[3]    = {INK, NROWS, BB};
        cuuint64_t strides[2] = {(cuuint64_t)INK * 4, (cuuint64_t)INK * NROWS * 4};
        cuuint32_t box[3]     = {32, 128, 1};
        cuuint32_t estr[3]    = {1, 1, 1};
        enc(&tmapA, CU_TENSOR_MAP_DATA_TYPE_FLOAT32, 3, (void*)x, dims, strides, box, estr,
            CU_TENSOR_MAP_INTERLEAVE_NONE, CU_TENSOR_MAP_SWIZZLE_128B,
            CU_TENSOR_MAP_L2_PROMOTION_L2_128B, CU_TENSOR_MAP_FLOAT_OOB_FILL_NONE);
    }

    // B tensormap: g_wT as [b=256][n=256][k=256] f32, box (32k, 256n, 1b), SW128
    CUtensorMap tmapB;
    {
        cuuint64_t dims[3]    = {INK, OUTN, BB};
        cuuint64_t strides[2] = {(cuuint64_t)INK * 4, (cuuint64_t)INK * OUTN * 4};
        cuuint32_t box[3]     = {32, 256, 1};
        cuuint32_t estr[3]    = {1, 1, 1};
        enc(&tmapB, CU_TENSOR_MAP_DATA_TYPE_FLOAT32, 3, wT_ptr, dims, strides, box, estr,
            CU_TENSOR_MAP_INTERLEAVE_NONE, CU_TENSOR_MAP_SWIZZLE_128B,
            CU_TENSOR_MAP_L2_PROMOTION_L2_128B, CU_TENSOR_MAP_FLOAT_OOB_FILL_NONE);
    }

    // pass 1: gather + transpose + tf32-round weights (vectorized, 64x64 tiles)
    alw_transpose<<<dim3(16, BB), 256>>>(indices, w);

    // pass 2: persistent GEMM, 2 CTAs per SM
    cudaFuncSetAttribute(alw_main,
                         cudaFuncAttributeMaxDynamicSharedMemorySize, SMEM_TOTAL);
    int grid = 2 * (nsm > 0 ? nsm : 148);
    if (grid > NTILES) grid = NTILES;
    alw_main<<<grid, 256, SMEM_TOTAL>>>(tmapA, tmapB, x, indices, w, bias, out);
}